// round 12
// baseline (speedup 1.0000x reference)
#include <cuda_runtime.h>
#include <cuda_fp16.h>
#include <cstdint>
#include <math.h>

#define NHEADS 8
#define DH     64
#define BATCH  4
#define NQS    1024
#define NKS    2048
#define DM     512
#define NSPLIT 4

// fp16 copies of inputs (converted once per run).
__device__ __half g_Xh  [(size_t)BATCH * NQS * DM];
__device__ __half g_Ctxh[(size_t)BATCH * NKS * DM];
__device__ __half g_Wqh[DM * DM];
__device__ __half g_Wkh[DM * DM];
__device__ __half g_Wvh[DM * DM];
__device__ __half g_Woh[DM * DM];
__device__ __half g_Biash[(size_t)BATCH * NQS * NKS];   // fp16 bias (16MB)
// Packed fp16 fragment buffers (mma-fragment order).
__device__ __half g_Qh[(size_t)BATCH * NQS * DM];
__device__ __half g_Kh[(size_t)BATCH * NKS * DM];
__device__ __half g_Vh[(size_t)BATCH * NKS * DM];
// Split-KV partial outputs (unnormalized, fp16) + (m, l) per row per split.
__device__ __half g_Parth[NSPLIT][(size_t)BATCH * NQS * DM];
__device__ float  g_M[NSPLIT][BATCH * NHEADS * NQS];
__device__ float  g_L[NSPLIT][BATCH * NHEADS * NQS];
// Merged attention output in fp16 (A operand of the output GEMM).
__device__ __half g_AOh[(size_t)BATCH * NQS * DM];

// ===========================================================================
// Helpers
// ===========================================================================
__device__ __forceinline__ uint32_t smem_u32(const void* p) {
    uint32_t a;
    asm("{ .reg .u64 t; cvta.to.shared.u64 t, %1; cvt.u32.u64 %0, t; }"
        : "=r"(a) : "l"(p));
    return a;
}
__device__ __forceinline__ void mma_f16(float c[4], const uint32_t a[4],
                                        uint32_t b0, uint32_t b1) {
    asm volatile(
        "mma.sync.aligned.m16n8k16.row.col.f32.f16.f16.f32 "
        "{%0,%1,%2,%3}, {%4,%5,%6,%7}, {%8,%9}, {%0,%1,%2,%3};"
        : "+f"(c[0]), "+f"(c[1]), "+f"(c[2]), "+f"(c[3])
        : "r"(a[0]), "r"(a[1]), "r"(a[2]), "r"(a[3]), "r"(b0), "r"(b1));
}
__device__ __forceinline__ void ldsm_x4(uint32_t r[4], uint32_t addr) {
    asm volatile("ldmatrix.sync.aligned.m8n8.x4.shared.b16 {%0,%1,%2,%3}, [%4];"
                 : "=r"(r[0]), "=r"(r[1]), "=r"(r[2]), "=r"(r[3]) : "r"(addr));
}
__device__ __forceinline__ void ldsm_x2(uint32_t r[2], uint32_t addr) {
    asm volatile("ldmatrix.sync.aligned.m8n8.x2.shared.b16 {%0,%1}, [%2];"
                 : "=r"(r[0]), "=r"(r[1]) : "r"(addr));
}
__device__ __forceinline__ uint32_t h2u(float lo, float hi) {
    __half2 v = __floats2half2_rn(lo, hi);
    return *(uint32_t*)&v;
}
__device__ __forceinline__ float2 u2f2(uint32_t u) {
    return __half22float2(*reinterpret_cast<const __half2*>(&u));
}
__device__ __forceinline__ void cp_async16(uint32_t s, const void* g) {
    asm volatile("cp.async.ca.shared.global [%0], [%1], 16;"
                 :: "r"(s), "l"(g) : "memory");
}
__device__ __forceinline__ void cp_commit() {
    asm volatile("cp.async.commit_group;" ::: "memory");
}
template<int N> __device__ __forceinline__ void cp_wait() {
    asm volatile("cp.async.wait_group %0;" :: "n"(N) : "memory");
}

// ===========================================================================
// Fused fp32 -> fp16 conversion: x, ctx, 4 weights, bias (one launch).
// ===========================================================================
#define NX4 (BATCH * NQS * DM / 4)          // 524288
#define NC4 (BATCH * NKS * DM / 4)          // 1048576
#define NW4 (DM * DM / 4)                   // 65536
#define NB4 (BATCH * NQS * NKS / 4)         // 2097152
#define CONV_BLOCKS ((NX4 + NC4 + 4 * NW4 + NB4) / 256)

__global__ __launch_bounds__(256) void conv_all_kernel(
    const float* __restrict__ x,  const float* __restrict__ ctx,
    const float* __restrict__ w0, const float* __restrict__ w1,
    const float* __restrict__ w2, const float* __restrict__ w3,
    const float* __restrict__ bias)
{
    const int i = blockIdx.x * 256 + threadIdx.x;
    const float* src;
    __half* dst;
    int j;
    if (i < NX4)                       { src = x;    dst = g_Xh;    j = i; }
    else if (i < NX4 + NC4)            { src = ctx;  dst = g_Ctxh;  j = i - NX4; }
    else if (i < NX4 + NC4 + 4 * NW4) {
        const int k = i - NX4 - NC4;
        const int t = k >> 16;
        j = k & 65535;
        src = (t == 0) ? w0 : (t == 1) ? w1 : (t == 2) ? w2 : w3;
        dst = (t == 0) ? g_Wqh : (t == 1) ? g_Wkh : (t == 2) ? g_Wvh : g_Woh;
    } else                             { src = bias; dst = g_Biash;
                                         j = i - NX4 - NC4 - 4 * NW4; }
    float4 v = ((const float4*)src)[j];
    *(uint2*)&dst[(size_t)j * 4] = make_uint2(h2u(v.x, v.y), h2u(v.z, v.w));
}

// ===========================================================================
// GEMM mainloop core: C[M,512] = A[M,512] @ W[512,512]^T, fp16 mma.
// CTA tile 128(M) x 64(N), BK=32 halves, 3-stage cp.async, 128 threads
// (4 warps, 2m x 2n, warp 64x32), ldmatrix frag loads, pitch 40 halves.
// PIPELINE INVARIANT: exactly one commit_group per iteration (empty commits
// in the tail) so cp_wait<2> always guarantees stage ks has landed.
// ===========================================================================
#define GBKH    32
#define GPITCHH 40
#define GA_H    (128 * GPITCHH)
#define GB_H    (64 * GPITCHH)
#define GSTG_H  (GA_H + GB_H)
#define GEMM_SMEM (3 * GSTG_H * 2)

__device__ __forceinline__ void gemm_mainloop(
    const __half* __restrict__ A, const __half* __restrict__ W,
    int m0, int n0, uint32_t sb, float acc[4][4][4],
    int lane, int wm, int wn)
{
    const int tid = threadIdx.x;

    auto stage_load = [&](int buf, int ks) {
        const int k0 = ks * GBKH;
        const uint32_t sA = sb + (uint32_t)(buf * GSTG_H) * 2u;
        const uint32_t sB = sA + (uint32_t)GA_H * 2u;
        #pragma unroll
        for (int i = 0; i < 4; i++) {
            int idx = tid + 128 * i;
            int r = idx >> 2, c = (idx & 3) * 8;
            cp_async16(sA + (uint32_t)(r * GPITCHH + c) * 2u,
                       A + (size_t)(m0 + r) * DM + k0 + c);
        }
        #pragma unroll
        for (int i = 0; i < 2; i++) {
            int idx = tid + 128 * i;
            int r = idx >> 2, c = (idx & 3) * 8;
            cp_async16(sB + (uint32_t)(r * GPITCHH + c) * 2u,
                       W + (size_t)(n0 + r) * DM + k0 + c);
        }
        cp_commit();
    };

    const int NST = DM / GBKH;   // 16
    stage_load(0, 0);
    stage_load(1, 1);
    stage_load(2, 2);

    const int aRow = ((lane >> 3) & 1) * 8 + (lane & 7);
    const int aK   = ((lane >> 4) & 1) * 8;
    const int bRow = lane & 7;
    const int bK   = ((lane >> 3) & 1) * 8;

    int buf = 0;
    for (int ks = 0; ks < NST; ++ks) {
        cp_wait<2>();
        __syncthreads();

        const uint32_t aBase = sb + (uint32_t)(buf * GSTG_H) * 2u;
        const uint32_t bBase = aBase + (uint32_t)GA_H * 2u;

        #pragma unroll
        for (int kst = 0; kst < 2; kst++) {
            uint32_t af[4][4];
            #pragma unroll
            for (int mt = 0; mt < 4; mt++)
                ldsm_x4(af[mt], aBase
                        + (uint32_t)((wm + mt * 16 + aRow) * GPITCHH
                                     + kst * 16 + aK) * 2u);
            uint32_t bf[4][2];
            #pragma unroll
            for (int nt = 0; nt < 4; nt++)
                ldsm_x2(bf[nt], bBase
                        + (uint32_t)((wn + nt * 8 + bRow) * GPITCHH
                                     + kst * 16 + bK) * 2u);
            #pragma unroll
            for (int mt = 0; mt < 4; mt++)
                #pragma unroll
                for (int nt = 0; nt < 4; nt++)
                    mma_f16(acc[mt][nt], af[mt], bf[nt][0], bf[nt][1]);
        }
        __syncthreads();
        if (ks + 3 < NST) stage_load(buf, ks + 3);
        else              cp_commit();
        buf = (buf == 2) ? 0 : buf + 1;
    }
}

// ---------------------------------------------------------------------------
// Fused Q/K/V projection GEMM. Linear grid: [0,256)=Q, [256,768)=K,
// [768,1280)=V. Epilogue packs mma-fragment layouts (Q pre-scaled 0.125).
// ---------------------------------------------------------------------------
__global__ __launch_bounds__(128, 4) void gemm_qkv_kernel()
{
    extern __shared__ __half smh[];
    const uint32_t sb = smem_u32(smh);

    const int tid  = threadIdx.x;
    const int w    = tid >> 5;
    const int lane = tid & 31;
    const int gid  = lane >> 2;
    const int tig  = lane & 3;
    const int wm   = (w >> 1) * 64;
    const int wn   = (w & 1) * 32;

    int id = blockIdx.x, mode;
    const __half *A, *W;
    __half *C;
    if (id < 256)      { mode = 1; A = g_Xh;   W = g_Wqh; C = g_Qh; }
    else if (id < 768) { mode = 2; id -= 256; A = g_Ctxh; W = g_Wkh; C = g_Kh; }
    else               { mode = 3; id -= 768; A = g_Ctxh; W = g_Wvh; C = g_Vh; }
    const int m0 = (id >> 3) * 128;
    const int n0 = (id & 7) * 64;

    float acc[4][4][4];
    #pragma unroll
    for (int mt = 0; mt < 4; mt++)
        #pragma unroll
        for (int nt = 0; nt < 4; nt++)
            #pragma unroll
            for (int q = 0; q < 4; q++) acc[mt][nt][q] = 0.f;

    gemm_mainloop(A, W, m0, n0, sb, acc, lane, wm, wn);

    #pragma unroll
    for (int mt = 0; mt < 4; mt++) {
        #pragma unroll
        for (int nt = 0; nt < 4; nt++) {
            #pragma unroll
            for (int q = 0; q < 4; q++) {
                const int m   = m0 + wm + mt * 16 + gid + 8 * (q >> 1);
                const int col = n0 + wn + nt * 8 + 2 * tig + (q & 1);
                const int h = col >> 6, d = col & 63;
                float val = acc[mt][nt][q];
                size_t idx;
                if (mode == 1) {
                    int b  = m >> 10, qq = m & 1023;
                    int t  = qq >> 4, g = qq & 7, rh = (qq >> 3) & 1;
                    int kk = d >> 4, hi = (d >> 3) & 1;
                    int tq = (d & 7) >> 1, ev = d & 1;
                    idx = ((((size_t)((b * 8 + h) * 64 + t) * 4 + kk) * 256)
                          + (g * 4 + tq) * 8 + (rh + 2 * hi) * 2 + ev);
                    val *= 0.125f;
                } else if (mode == 2) {
                    int b = m >> 11, n = m & 2047;
                    int kt = n >> 6, ri = n & 63;
                    int nt2 = ri >> 3, g = ri & 7;
                    int kk = d >> 4, hi = (d >> 3) & 1;
                    int t = (d & 7) >> 1, ev = d & 1;
                    idx = (size_t)((b * 32 + kt) * 8 + h) * 4096
                          + (kk * 8 + nt2) * 128 + (g * 4 + t) * 4
                          + hi * 2 + ev;
                } else {
                    int b = m >> 11, n = m & 2047;
                    int kt = n >> 6, kr = n & 63;
                    int kk = kr >> 4, hi = (kr >> 3) & 1;
                    int t = (kr & 7) >> 1, ev = kr & 1;
                    int nt2 = d >> 3, g = d & 7;
                    idx = (size_t)((b * 32 + kt) * 8 + h) * 4096
                          + (kk * 8 + nt2) * 128 + (g * 4 + t) * 4
                          + hi * 2 + ev;
                }
                C[idx] = __float2half_rn(val);
            }
        }
    }
}

// ---------------------------------------------------------------------------
// Output GEMM: out = g_AOh @ Wo^T + bo.  grid (8 n, 32 m).
// ---------------------------------------------------------------------------
__global__ __launch_bounds__(128, 4) void gemm_o_kernel(
    const float* __restrict__ bias, float* __restrict__ out)
{
    extern __shared__ __half smh[];
    const uint32_t sb = smem_u32(smh);

    const int tid  = threadIdx.x;
    const int w    = tid >> 5;
    const int lane = tid & 31;
    const int gid  = lane >> 2;
    const int tig  = lane & 3;
    const int wm   = (w >> 1) * 64;
    const int wn   = (w & 1) * 32;
    const int n0   = blockIdx.x * 64;
    const int m0   = blockIdx.y * 128;

    float acc[4][4][4];
    #pragma unroll
    for (int mt = 0; mt < 4; mt++)
        #pragma unroll
        for (int nt = 0; nt < 4; nt++)
            #pragma unroll
            for (int q = 0; q < 4; q++) acc[mt][nt][q] = 0.f;

    gemm_mainloop(g_AOh, g_Woh, m0, n0, sb, acc, lane, wm, wn);

    #pragma unroll
    for (int mt = 0; mt < 4; mt++) {
        const int r0 = m0 + wm + mt * 16 + gid;
        #pragma unroll
        for (int nt = 0; nt < 4; nt++) {
            const int col = n0 + wn + nt * 8 + 2 * tig;
            const float b0 = bias[col], b1 = bias[col + 1];
            *(float2*)(out + (size_t)r0 * DM + col) =
                make_float2(acc[mt][nt][0] + b0, acc[mt][nt][1] + b1);
            *(float2*)(out + (size_t)(r0 + 8) * DM + col) =
                make_float2(acc[mt][nt][2] + b0, acc[mt][nt][3] + b1);
        }
    }
}

// ===========================================================================
// Flash attention, fp16 mma, f32 accumulate, P in registers, SPLIT-KV x4.
// Bias read as fp16 (half the L2 traffic); partials stored fp16.
// ===========================================================================
#define ATTN_SMEM 49152
#define KV_SPLIT_TILES (32 / NSPLIT)

__global__ __launch_bounds__(128, 3) void attn_kernel()
{
    extern __shared__ __half smha[];
    const uint32_t sb = smem_u32(smha);

    const int tid   = threadIdx.x;
    const int w     = tid >> 5;
    const int lane  = tid & 31;
    const int gid   = lane >> 2;
    const int tig   = lane & 3;
    const int split = blockIdx.x & (NSPLIT - 1);
    const int qt    = blockIdx.x / NSPLIT;
    const int q0    = qt * 128;
    const int h     = blockIdx.y;
    const int b     = blockIdx.z;
    const int kb0   = split * KV_SPLIT_TILES;

    {
        const __half* gq = g_Qh + (size_t)((b * 8 + h) * 64 + qt * 8) * 1024;
        #pragma unroll
        for (int i = 0; i < 8; i++) {
            int off = i * 1024 + tid * 8;
            cp_async16(sb + (16384 + off) * 2, gq + off);
        }
    }
    {
        const __half* gk = g_Kh + ((size_t)(b * 32 + kb0) * 8 + h) * 4096;
        const __half* gv = g_Vh + ((size_t)(b * 32 + kb0) * 8 + h) * 4096;
        #pragma unroll
        for (int i = 0; i < 4; i++) {
            int off = i * 1024 + tid * 8;
            cp_async16(sb + ((kb0 & 1) * 4096 + off) * 2, gk + off);
            cp_async16(sb + (8192 + (kb0 & 1) * 4096 + off) * 2, gv + off);
        }
    }
    cp_commit();

    float o[2][8][4];
    #pragma unroll
    for (int mt = 0; mt < 2; mt++)
        #pragma unroll
        for (int nt = 0; nt < 8; nt++)
            #pragma unroll
            for (int q = 0; q < 4; q++) o[mt][nt][q] = 0.f;
    float mx[2][2] = {{-1e30f, -1e30f}, {-1e30f, -1e30f}};
    float ls[2][2] = {{0.f, 0.f}, {0.f, 0.f}};

    const int qbase = 16384 + w * 2048;

    for (int kb = kb0; kb < kb0 + KV_SPLIT_TILES; kb++) {
        cp_wait<0>();
        __syncthreads();

        if (kb + 1 < kb0 + KV_SPLIT_TILES) {
            const int nb = (kb + 1) & 1;
            const __half* gk = g_Kh + ((size_t)(b * 32 + kb + 1) * 8 + h) * 4096;
            const __half* gv = g_Vh + ((size_t)(b * 32 + kb + 1) * 8 + h) * 4096;
            #pragma unroll
            for (int i = 0; i < 4; i++) {
                int off = i * 1024 + tid * 8;
                cp_async16(sb + (nb * 4096 + off) * 2, gk + off);
                cp_async16(sb + (8192 + nb * 4096 + off) * 2, gv + off);
            }
            cp_commit();
        }

        const int kbo = (kb & 1) * 4096;

        float s[2][8][4];
        #pragma unroll
        for (int mt = 0; mt < 2; mt++)
            #pragma unroll
            for (int nt = 0; nt < 8; nt++)
                #pragma unroll
                for (int q = 0; q < 4; q++) s[mt][nt][q] = 0.f;

        #pragma unroll
        for (int kk = 0; kk < 4; kk++) {
            uint32_t af[2][4];
            #pragma unroll
            for (int mt = 0; mt < 2; mt++) {
                float4 a4 = *(const float4*)&smha[qbase + mt * 1024
                                                  + kk * 256 + lane * 8];
                af[mt][0] = __float_as_uint(a4.x); af[mt][1] = __float_as_uint(a4.y);
                af[mt][2] = __float_as_uint(a4.z); af[mt][3] = __float_as_uint(a4.w);
            }
            #pragma unroll
            for (int nt = 0; nt < 8; nt++) {
                uint2 k2 = *(const uint2*)&smha[kbo + (kk * 8 + nt) * 128 + lane * 4];
                mma_f16(s[0][nt], af[0], k2.x, k2.y);
                mma_f16(s[1][nt], af[1], k2.x, k2.y);
            }
        }

        #pragma unroll
        for (int mt = 0; mt < 2; mt++) {
            const __half* bLo = g_Biash
                + ((size_t)b * NQS + q0 + 32 * w + 16 * mt + gid) * NKS + kb * 64;
            const __half* bHi = bLo + 8 * (size_t)NKS;

            float rmLo = -1e30f, rmHi = -1e30f;
            #pragma unroll
            for (int nt = 0; nt < 8; nt++) {
                float2 bl = u2f2(*(const uint32_t*)(bLo + nt * 8 + 2 * tig));
                float2 bh = u2f2(*(const uint32_t*)(bHi + nt * 8 + 2 * tig));
                s[mt][nt][0] += bl.x;  s[mt][nt][1] += bl.y;
                s[mt][nt][2] += bh.x;  s[mt][nt][3] += bh.y;
                rmLo = fmaxf(rmLo, fmaxf(s[mt][nt][0], s[mt][nt][1]));
                rmHi = fmaxf(rmHi, fmaxf(s[mt][nt][2], s[mt][nt][3]));
            }
            rmLo = fmaxf(rmLo, __shfl_xor_sync(0xffffffffu, rmLo, 1));
            rmLo = fmaxf(rmLo, __shfl_xor_sync(0xffffffffu, rmLo, 2));
            rmHi = fmaxf(rmHi, __shfl_xor_sync(0xffffffffu, rmHi, 1));
            rmHi = fmaxf(rmHi, __shfl_xor_sync(0xffffffffu, rmHi, 2));

            const float mnLo = fmaxf(mx[mt][0], rmLo);
            const float mnHi = fmaxf(mx[mt][1], rmHi);
            const float corrLo = __expf(mx[mt][0] - mnLo);
            const float corrHi = __expf(mx[mt][1] - mnHi);
            mx[mt][0] = mnLo; mx[mt][1] = mnHi;

            float rsLo = 0.f, rsHi = 0.f;
            #pragma unroll
            for (int nt = 0; nt < 8; nt++) {
                float p0 = __expf(s[mt][nt][0] - mnLo);
                float p1 = __expf(s[mt][nt][1] - mnLo);
                float p2 = __expf(s[mt][nt][2] - mnHi);
                float p3 = __expf(s[mt][nt][3] - mnHi);
                rsLo += p0 + p1;
                rsHi += p2 + p3;
                s[mt][nt][0] = p0; s[mt][nt][1] = p1;
                s[mt][nt][2] = p2; s[mt][nt][3] = p3;
                o[mt][nt][0] *= corrLo; o[mt][nt][1] *= corrLo;
                o[mt][nt][2] *= corrHi; o[mt][nt][3] *= corrHi;
            }
            rsLo += __shfl_xor_sync(0xffffffffu, rsLo, 1);
            rsLo += __shfl_xor_sync(0xffffffffu, rsLo, 2);
            rsHi += __shfl_xor_sync(0xffffffffu, rsHi, 1);
            rsHi += __shfl_xor_sync(0xffffffffu, rsHi, 2);
            ls[mt][0] = ls[mt][0] * corrLo + rsLo;
            ls[mt][1] = ls[mt][1] * corrHi + rsHi;
        }

        #pragma unroll
        for (int kk = 0; kk < 4; kk++) {
            uint32_t af[2][4];
            #pragma unroll
            for (int mt = 0; mt < 2; mt++) {
                af[mt][0] = h2u(s[mt][2 * kk][0],     s[mt][2 * kk][1]);
                af[mt][1] = h2u(s[mt][2 * kk][2],     s[mt][2 * kk][3]);
                af[mt][2] = h2u(s[mt][2 * kk + 1][0], s[mt][2 * kk + 1][1]);
                af[mt][3] = h2u(s[mt][2 * kk + 1][2], s[mt][2 * kk + 1][3]);
            }
            #pragma unroll
            for (int nt = 0; nt < 8; nt++) {
                uint2 v2 = *(const uint2*)&smha[8192 + kbo
                                                + (kk * 8 + nt) * 128 + lane * 4];
                mma_f16(o[0][nt], af[0], v2.x, v2.y);
                mma_f16(o[1][nt], af[1], v2.x, v2.y);
            }
        }
    }

    // store unnormalized partials in fp16 + (m, l)
    __half* Opart = g_Parth[split];
    #pragma unroll
    for (int mt = 0; mt < 2; mt++) {
        const int rowLo = q0 + 32 * w + 16 * mt + gid;
        __half* OgLo = Opart + ((size_t)b * NQS + rowLo) * DM + h * DH;
        __half* OgHi = OgLo + 8 * (size_t)DM;
        #pragma unroll
        for (int nt = 0; nt < 8; nt++) {
            int col = nt * 8 + 2 * tig;
            *(uint32_t*)(OgLo + col) = h2u(o[mt][nt][0], o[mt][nt][1]);
            *(uint32_t*)(OgHi + col) = h2u(o[mt][nt][2], o[mt][nt][3]);
        }
        if (tig == 0) {
            int mi = (b * 8 + h) * 1024 + rowLo;
            g_M[split][mi]     = mx[mt][0];
            g_L[split][mi]     = ls[mt][0];
            g_M[split][mi + 8] = mx[mt][1];
            g_L[split][mi + 8] = ls[mt][1];
        }
    }
}

// ===========================================================================
// Merge the NSPLIT KV splits (fp16 partials); emit fp16 A operand.
// ===========================================================================
__global__ __launch_bounds__(256) void merge_kernel()
{
    const size_t i = (size_t)blockIdx.x * 256 + threadIdx.x;   // per half2
    const size_t e = i * 2;
    const size_t row = e / DM;
    const int d  = (int)(e % DM);
    const int b  = (int)(row >> 10);
    const int q  = (int)(row & 1023);
    const int h  = d >> 6;
    const int mi = (b * 8 + h) * 1024 + q;

    float m[NSPLIT], l[NSPLIT];
    float ms = -1e30f;
    #pragma unroll
    for (int s = 0; s < NSPLIT; s++) {
        m[s] = g_M[s][mi];
        l[s] = g_L[s][mi];
        ms = fmaxf(ms, m[s]);
    }
    float den = 0.f;
    float a[NSPLIT];
    #pragma unroll
    for (int s = 0; s < NSPLIT; s++) {
        a[s] = __expf(m[s] - ms);
        den += l[s] * a[s];
    }
    const float inv = 1.f / den;

    float ox = 0.f, oy = 0.f;
    #pragma unroll
    for (int s = 0; s < NSPLIT; s++) {
        const float2 p = u2f2(*(const uint32_t*)&g_Parth[s][e]);
        ox += p.x * a[s];
        oy += p.y * a[s];
    }
    *(uint32_t*)&g_AOh[e] = h2u(ox * inv, oy * inv);
}

// ---------------------------------------------------------------------------
// Launch
// ---------------------------------------------------------------------------
extern "C" void kernel_launch(void* const* d_in, const int* in_sizes, int n_in,
                              void* d_out, int out_size)
{
    const float* x    = (const float*)d_in[0];
    const float* ctx  = (const float*)d_in[1];
    const float* bias = (const float*)d_in[2];
    const float* Wq   = (const float*)d_in[3];
    const float* Wk   = (const float*)d_in[4];
    const float* Wv   = (const float*)d_in[5];
    const float* Wo   = (const float*)d_in[6];
    const float* bo   = (const float*)d_in[7];
    float* out = (float*)d_out;

    cudaFuncSetAttribute(gemm_qkv_kernel,
                         cudaFuncAttributeMaxDynamicSharedMemorySize, GEMM_SMEM);
    cudaFuncSetAttribute(gemm_o_kernel,
                         cudaFuncAttributeMaxDynamicSharedMemorySize, GEMM_SMEM);
    cudaFuncSetAttribute(attn_kernel,
                         cudaFuncAttributeMaxDynamicSharedMemorySize, ATTN_SMEM);

    conv_all_kernel<<<CONV_BLOCKS, 256>>>(x, ctx, Wq, Wk, Wv, Wo, bias);
    gemm_qkv_kernel<<<1280, 128, GEMM_SMEM>>>();
    attn_kernel<<<dim3((NQS / 128) * NSPLIT, NHEADS, BATCH),
                  dim3(128), ATTN_SMEM>>>();
    merge_kernel<<<(BATCH * NQS * DM / 2) / 256, 256>>>();
    gemm_o_kernel<<<dim3(8, 32), 128, GEMM_SMEM>>>(bo, out);
}

// round 13
// speedup vs baseline: 1.0369x; 1.0369x over previous
#include <cuda_runtime.h>
#include <cuda_fp16.h>
#include <cstdint>
#include <math.h>

#define NHEADS 8
#define DH     64
#define BATCH  4
#define NQS    1024
#define NKS    2048
#define DM     512
#define NSPLIT 4

// fp16 copies of inputs (converted once per run).
__device__ __half g_Xh  [(size_t)BATCH * NQS * DM];
__device__ __half g_Ctxh[(size_t)BATCH * NKS * DM];
__device__ __half g_Wqh[DM * DM];
__device__ __half g_Wkh[DM * DM];
__device__ __half g_Wvh[DM * DM];
__device__ __half g_Woh[DM * DM];
// Packed fp16 fragment buffers (mma-fragment order).
__device__ __half g_Qh[(size_t)BATCH * NQS * DM];
__device__ __half g_Kh[(size_t)BATCH * NKS * DM];
__device__ __half g_Vh[(size_t)BATCH * NKS * DM];
// Split-KV partial outputs (unnormalized, fp16) + (m, l) per row per split.
__device__ __half g_Parth[NSPLIT][(size_t)BATCH * NQS * DM];
__device__ float  g_M[NSPLIT][BATCH * NHEADS * NQS];
__device__ float  g_L[NSPLIT][BATCH * NHEADS * NQS];
// Merged attention output in fp16 (A operand of the output GEMM).
__device__ __half g_AOh[(size_t)BATCH * NQS * DM];

// ===========================================================================
// Helpers
// ===========================================================================
__device__ __forceinline__ uint32_t smem_u32(const void* p) {
    uint32_t a;
    asm("{ .reg .u64 t; cvta.to.shared.u64 t, %1; cvt.u32.u64 %0, t; }"
        : "=r"(a) : "l"(p));
    return a;
}
__device__ __forceinline__ void mma_f16(float c[4], const uint32_t a[4],
                                        uint32_t b0, uint32_t b1) {
    asm volatile(
        "mma.sync.aligned.m16n8k16.row.col.f32.f16.f16.f32 "
        "{%0,%1,%2,%3}, {%4,%5,%6,%7}, {%8,%9}, {%0,%1,%2,%3};"
        : "+f"(c[0]), "+f"(c[1]), "+f"(c[2]), "+f"(c[3])
        : "r"(a[0]), "r"(a[1]), "r"(a[2]), "r"(a[3]), "r"(b0), "r"(b1));
}
__device__ __forceinline__ void ldsm_x4(uint32_t r[4], uint32_t addr) {
    asm volatile("ldmatrix.sync.aligned.m8n8.x4.shared.b16 {%0,%1,%2,%3}, [%4];"
                 : "=r"(r[0]), "=r"(r[1]), "=r"(r[2]), "=r"(r[3]) : "r"(addr));
}
__device__ __forceinline__ void ldsm_x2(uint32_t r[2], uint32_t addr) {
    asm volatile("ldmatrix.sync.aligned.m8n8.x2.shared.b16 {%0,%1}, [%2];"
                 : "=r"(r[0]), "=r"(r[1]) : "r"(addr));
}
__device__ __forceinline__ uint32_t h2u(float lo, float hi) {
    __half2 v = __floats2half2_rn(lo, hi);
    return *(uint32_t*)&v;
}
__device__ __forceinline__ float2 u2f2(uint32_t u) {
    return __half22float2(*reinterpret_cast<const __half2*>(&u));
}
__device__ __forceinline__ void cp_async16(uint32_t s, const void* g) {
    asm volatile("cp.async.ca.shared.global [%0], [%1], 16;"
                 :: "r"(s), "l"(g) : "memory");
}
__device__ __forceinline__ void cp_commit() {
    asm volatile("cp.async.commit_group;" ::: "memory");
}
template<int N> __device__ __forceinline__ void cp_wait() {
    asm volatile("cp.async.wait_group %0;" :: "n"(N) : "memory");
}

// ===========================================================================
// Fused fp32 -> fp16 conversion of x, ctx and the 4 weights (one launch).
// ===========================================================================
#define NX4 (BATCH * NQS * DM / 4)          // 524288
#define NC4 (BATCH * NKS * DM / 4)          // 1048576
#define NW4 (DM * DM / 4)                   // 65536
#define CONV_BLOCKS ((NX4 + NC4 + 4 * NW4) / 256)

__global__ __launch_bounds__(256) void conv_all_kernel(
    const float* __restrict__ x,  const float* __restrict__ ctx,
    const float* __restrict__ w0, const float* __restrict__ w1,
    const float* __restrict__ w2, const float* __restrict__ w3)
{
    const int i = blockIdx.x * 256 + threadIdx.x;
    const float* src;
    __half* dst;
    int j;
    if (i < NX4)                 { src = x;   dst = g_Xh;   j = i; }
    else if (i < NX4 + NC4)      { src = ctx; dst = g_Ctxh; j = i - NX4; }
    else {
        const int k = i - NX4 - NC4;
        const int t = k >> 16;
        j = k & 65535;
        src = (t == 0) ? w0 : (t == 1) ? w1 : (t == 2) ? w2 : w3;
        dst = (t == 0) ? g_Wqh : (t == 1) ? g_Wkh : (t == 2) ? g_Wvh : g_Woh;
    }
    float4 v = ((const float4*)src)[j];
    *(uint2*)&dst[(size_t)j * 4] = make_uint2(h2u(v.x, v.y), h2u(v.z, v.w));
}

// ===========================================================================
// GEMM mainloop core: C[M,512] = A[M,512] @ W[512,512]^T, fp16 mma.
// CTA tile 128(M) x 64(N), BK=32 halves, 3-stage cp.async, 128 threads
// (4 warps, 2m x 2n, warp 64x32), ldmatrix frag loads, pitch 40 halves.
// PIPELINE INVARIANT: exactly one commit_group per iteration (empty commits
// in the tail) so cp_wait<2> always guarantees stage ks has landed.
// ===========================================================================
#define GBKH    32
#define GPITCHH 40
#define GA_H    (128 * GPITCHH)
#define GB_H    (64 * GPITCHH)
#define GSTG_H  (GA_H + GB_H)
#define GEMM_SMEM (3 * GSTG_H * 2)

__device__ __forceinline__ void gemm_mainloop(
    const __half* __restrict__ A, const __half* __restrict__ W,
    int m0, int n0, uint32_t sb, float acc[4][4][4],
    int lane, int wm, int wn)
{
    const int tid = threadIdx.x;

    auto stage_load = [&](int buf, int ks) {
        const int k0 = ks * GBKH;
        const uint32_t sA = sb + (uint32_t)(buf * GSTG_H) * 2u;
        const uint32_t sB = sA + (uint32_t)GA_H * 2u;
        #pragma unroll
        for (int i = 0; i < 4; i++) {
            int idx = tid + 128 * i;
            int r = idx >> 2, c = (idx & 3) * 8;
            cp_async16(sA + (uint32_t)(r * GPITCHH + c) * 2u,
                       A + (size_t)(m0 + r) * DM + k0 + c);
        }
        #pragma unroll
        for (int i = 0; i < 2; i++) {
            int idx = tid + 128 * i;
            int r = idx >> 2, c = (idx & 3) * 8;
            cp_async16(sB + (uint32_t)(r * GPITCHH + c) * 2u,
                       W + (size_t)(n0 + r) * DM + k0 + c);
        }
        cp_commit();
    };

    const int NST = DM / GBKH;   // 16
    stage_load(0, 0);
    stage_load(1, 1);
    stage_load(2, 2);

    const int aRow = ((lane >> 3) & 1) * 8 + (lane & 7);
    const int aK   = ((lane >> 4) & 1) * 8;
    const int bRow = lane & 7;
    const int bK   = ((lane >> 3) & 1) * 8;

    int buf = 0;
    for (int ks = 0; ks < NST; ++ks) {
        cp_wait<2>();
        __syncthreads();

        const uint32_t aBase = sb + (uint32_t)(buf * GSTG_H) * 2u;
        const uint32_t bBase = aBase + (uint32_t)GA_H * 2u;

        #pragma unroll
        for (int kst = 0; kst < 2; kst++) {
            uint32_t af[4][4];
            #pragma unroll
            for (int mt = 0; mt < 4; mt++)
                ldsm_x4(af[mt], aBase
                        + (uint32_t)((wm + mt * 16 + aRow) * GPITCHH
                                     + kst * 16 + aK) * 2u);
            uint32_t bf[4][2];
            #pragma unroll
            for (int nt = 0; nt < 4; nt++)
                ldsm_x2(bf[nt], bBase
                        + (uint32_t)((wn + nt * 8 + bRow) * GPITCHH
                                     + kst * 16 + bK) * 2u);
            #pragma unroll
            for (int mt = 0; mt < 4; mt++)
                #pragma unroll
                for (int nt = 0; nt < 4; nt++)
                    mma_f16(acc[mt][nt], af[mt], bf[nt][0], bf[nt][1]);
        }
        __syncthreads();
        if (ks + 3 < NST) stage_load(buf, ks + 3);
        else              cp_commit();
        buf = (buf == 2) ? 0 : buf + 1;
    }
}

// ---------------------------------------------------------------------------
// Fused Q/K/V projection GEMM. Linear grid: [0,256)=Q, [256,768)=K,
// [768,1280)=V. Epilogue packs mma-fragment layouts (Q pre-scaled 0.125).
// ---------------------------------------------------------------------------
__global__ __launch_bounds__(128, 4) void gemm_qkv_kernel()
{
    extern __shared__ __half smh[];
    const uint32_t sb = smem_u32(smh);

    const int tid  = threadIdx.x;
    const int w    = tid >> 5;
    const int lane = tid & 31;
    const int gid  = lane >> 2;
    const int tig  = lane & 3;
    const int wm   = (w >> 1) * 64;
    const int wn   = (w & 1) * 32;

    int id = blockIdx.x, mode;
    const __half *A, *W;
    __half *C;
    if (id < 256)      { mode = 1; A = g_Xh;   W = g_Wqh; C = g_Qh; }
    else if (id < 768) { mode = 2; id -= 256; A = g_Ctxh; W = g_Wkh; C = g_Kh; }
    else               { mode = 3; id -= 768; A = g_Ctxh; W = g_Wvh; C = g_Vh; }
    const int m0 = (id >> 3) * 128;
    const int n0 = (id & 7) * 64;

    float acc[4][4][4];
    #pragma unroll
    for (int mt = 0; mt < 4; mt++)
        #pragma unroll
        for (int nt = 0; nt < 4; nt++)
            #pragma unroll
            for (int q = 0; q < 4; q++) acc[mt][nt][q] = 0.f;

    gemm_mainloop(A, W, m0, n0, sb, acc, lane, wm, wn);

    #pragma unroll
    for (int mt = 0; mt < 4; mt++) {
        #pragma unroll
        for (int nt = 0; nt < 4; nt++) {
            #pragma unroll
            for (int q = 0; q < 4; q++) {
                const int m   = m0 + wm + mt * 16 + gid + 8 * (q >> 1);
                const int col = n0 + wn + nt * 8 + 2 * tig + (q & 1);
                const int h = col >> 6, d = col & 63;
                float val = acc[mt][nt][q];
                size_t idx;
                if (mode == 1) {
                    int b  = m >> 10, qq = m & 1023;
                    int t  = qq >> 4, g = qq & 7, rh = (qq >> 3) & 1;
                    int kk = d >> 4, hi = (d >> 3) & 1;
                    int tq = (d & 7) >> 1, ev = d & 1;
                    idx = ((((size_t)((b * 8 + h) * 64 + t) * 4 + kk) * 256)
                          + (g * 4 + tq) * 8 + (rh + 2 * hi) * 2 + ev);
                    val *= 0.125f;
                } else if (mode == 2) {
                    int b = m >> 11, n = m & 2047;
                    int kt = n >> 6, ri = n & 63;
                    int nt2 = ri >> 3, g = ri & 7;
                    int kk = d >> 4, hi = (d >> 3) & 1;
                    int t = (d & 7) >> 1, ev = d & 1;
                    idx = (size_t)((b * 32 + kt) * 8 + h) * 4096
                          + (kk * 8 + nt2) * 128 + (g * 4 + t) * 4
                          + hi * 2 + ev;
                } else {
                    int b = m >> 11, n = m & 2047;
                    int kt = n >> 6, kr = n & 63;
                    int kk = kr >> 4, hi = (kr >> 3) & 1;
                    int t = (kr & 7) >> 1, ev = kr & 1;
                    int nt2 = d >> 3, g = d & 7;
                    idx = (size_t)((b * 32 + kt) * 8 + h) * 4096
                          + (kk * 8 + nt2) * 128 + (g * 4 + t) * 4
                          + hi * 2 + ev;
                }
                C[idx] = __float2half_rn(val);
            }
        }
    }
}

// ---------------------------------------------------------------------------
// Output GEMM: out = g_AOh @ Wo^T + bo.  grid (8 n, 32 m).
// ---------------------------------------------------------------------------
__global__ __launch_bounds__(128, 4) void gemm_o_kernel(
    const float* __restrict__ bias, float* __restrict__ out)
{
    extern __shared__ __half smh[];
    const uint32_t sb = smem_u32(smh);

    const int tid  = threadIdx.x;
    const int w    = tid >> 5;
    const int lane = tid & 31;
    const int gid  = lane >> 2;
    const int tig  = lane & 3;
    const int wm   = (w >> 1) * 64;
    const int wn   = (w & 1) * 32;
    const int n0   = blockIdx.x * 64;
    const int m0   = blockIdx.y * 128;

    float acc[4][4][4];
    #pragma unroll
    for (int mt = 0; mt < 4; mt++)
        #pragma unroll
        for (int nt = 0; nt < 4; nt++)
            #pragma unroll
            for (int q = 0; q < 4; q++) acc[mt][nt][q] = 0.f;

    gemm_mainloop(g_AOh, g_Woh, m0, n0, sb, acc, lane, wm, wn);

    #pragma unroll
    for (int mt = 0; mt < 4; mt++) {
        const int r0 = m0 + wm + mt * 16 + gid;
        #pragma unroll
        for (int nt = 0; nt < 4; nt++) {
            const int col = n0 + wn + nt * 8 + 2 * tig;
            const float b0 = bias[col], b1 = bias[col + 1];
            *(float2*)(out + (size_t)r0 * DM + col) =
                make_float2(acc[mt][nt][0] + b0, acc[mt][nt][1] + b1);
            *(float2*)(out + (size_t)(r0 + 8) * DM + col) =
                make_float2(acc[mt][nt][2] + b0, acc[mt][nt][3] + b1);
        }
    }
}

// ===========================================================================
// Flash attention, fp16 mma, f32 accumulate, P in registers, SPLIT-KV x4.
// Bias read fp32 (L2-resident; R12 showed fp16 bias doesn't pay).
// Partials stored fp16 (halves store+merge traffic; measured safe).
// ===========================================================================
#define ATTN_SMEM 49152
#define KV_SPLIT_TILES (32 / NSPLIT)

__global__ __launch_bounds__(128, 3) void attn_kernel(const float* __restrict__ bias)
{
    extern __shared__ __half smha[];
    const uint32_t sb = smem_u32(smha);

    const int tid   = threadIdx.x;
    const int w     = tid >> 5;
    const int lane  = tid & 31;
    const int gid   = lane >> 2;
    const int tig   = lane & 3;
    const int split = blockIdx.x & (NSPLIT - 1);
    const int qt    = blockIdx.x / NSPLIT;
    const int q0    = qt * 128;
    const int h     = blockIdx.y;
    const int b     = blockIdx.z;
    const int kb0   = split * KV_SPLIT_TILES;

    {
        const __half* gq = g_Qh + (size_t)((b * 8 + h) * 64 + qt * 8) * 1024;
        #pragma unroll
        for (int i = 0; i < 8; i++) {
            int off = i * 1024 + tid * 8;
            cp_async16(sb + (16384 + off) * 2, gq + off);
        }
    }
    {
        const __half* gk = g_Kh + ((size_t)(b * 32 + kb0) * 8 + h) * 4096;
        const __half* gv = g_Vh + ((size_t)(b * 32 + kb0) * 8 + h) * 4096;
        #pragma unroll
        for (int i = 0; i < 4; i++) {
            int off = i * 1024 + tid * 8;
            cp_async16(sb + ((kb0 & 1) * 4096 + off) * 2, gk + off);
            cp_async16(sb + (8192 + (kb0 & 1) * 4096 + off) * 2, gv + off);
        }
    }
    cp_commit();

    float o[2][8][4];
    #pragma unroll
    for (int mt = 0; mt < 2; mt++)
        #pragma unroll
        for (int nt = 0; nt < 8; nt++)
            #pragma unroll
            for (int q = 0; q < 4; q++) o[mt][nt][q] = 0.f;
    float mx[2][2] = {{-1e30f, -1e30f}, {-1e30f, -1e30f}};
    float ls[2][2] = {{0.f, 0.f}, {0.f, 0.f}};

    const int qbase = 16384 + w * 2048;

    for (int kb = kb0; kb < kb0 + KV_SPLIT_TILES; kb++) {
        cp_wait<0>();
        __syncthreads();

        if (kb + 1 < kb0 + KV_SPLIT_TILES) {
            const int nb = (kb + 1) & 1;
            const __half* gk = g_Kh + ((size_t)(b * 32 + kb + 1) * 8 + h) * 4096;
            const __half* gv = g_Vh + ((size_t)(b * 32 + kb + 1) * 8 + h) * 4096;
            #pragma unroll
            for (int i = 0; i < 4; i++) {
                int off = i * 1024 + tid * 8;
                cp_async16(sb + (nb * 4096 + off) * 2, gk + off);
                cp_async16(sb + (8192 + nb * 4096 + off) * 2, gv + off);
            }
            cp_commit();
        }

        const int kbo = (kb & 1) * 4096;

        float s[2][8][4];
        #pragma unroll
        for (int mt = 0; mt < 2; mt++)
            #pragma unroll
            for (int nt = 0; nt < 8; nt++)
                #pragma unroll
                for (int q = 0; q < 4; q++) s[mt][nt][q] = 0.f;

        #pragma unroll
        for (int kk = 0; kk < 4; kk++) {
            uint32_t af[2][4];
            #pragma unroll
            for (int mt = 0; mt < 2; mt++) {
                float4 a4 = *(const float4*)&smha[qbase + mt * 1024
                                                  + kk * 256 + lane * 8];
                af[mt][0] = __float_as_uint(a4.x); af[mt][1] = __float_as_uint(a4.y);
                af[mt][2] = __float_as_uint(a4.z); af[mt][3] = __float_as_uint(a4.w);
            }
            #pragma unroll
            for (int nt = 0; nt < 8; nt++) {
                uint2 k2 = *(const uint2*)&smha[kbo + (kk * 8 + nt) * 128 + lane * 4];
                mma_f16(s[0][nt], af[0], k2.x, k2.y);
                mma_f16(s[1][nt], af[1], k2.x, k2.y);
            }
        }

        #pragma unroll
        for (int mt = 0; mt < 2; mt++) {
            const float* bLo = bias
                + ((size_t)b * NQS + q0 + 32 * w + 16 * mt + gid) * NKS + kb * 64;
            const float* bHi = bLo + 8 * (size_t)NKS;

            float rmLo = -1e30f, rmHi = -1e30f;
            #pragma unroll
            for (int nt = 0; nt < 8; nt++) {
                float2 bl = *(const float2*)(bLo + nt * 8 + 2 * tig);
                float2 bh = *(const float2*)(bHi + nt * 8 + 2 * tig);
                s[mt][nt][0] += bl.x;  s[mt][nt][1] += bl.y;
                s[mt][nt][2] += bh.x;  s[mt][nt][3] += bh.y;
                rmLo = fmaxf(rmLo, fmaxf(s[mt][nt][0], s[mt][nt][1]));
                rmHi = fmaxf(rmHi, fmaxf(s[mt][nt][2], s[mt][nt][3]));
            }
            rmLo = fmaxf(rmLo, __shfl_xor_sync(0xffffffffu, rmLo, 1));
            rmLo = fmaxf(rmLo, __shfl_xor_sync(0xffffffffu, rmLo, 2));
            rmHi = fmaxf(rmHi, __shfl_xor_sync(0xffffffffu, rmHi, 1));
            rmHi = fmaxf(rmHi, __shfl_xor_sync(0xffffffffu, rmHi, 2));

            const float mnLo = fmaxf(mx[mt][0], rmLo);
            const float mnHi = fmaxf(mx[mt][1], rmHi);
            const float corrLo = __expf(mx[mt][0] - mnLo);
            const float corrHi = __expf(mx[mt][1] - mnHi);
            mx[mt][0] = mnLo; mx[mt][1] = mnHi;

            float rsLo = 0.f, rsHi = 0.f;
            #pragma unroll
            for (int nt = 0; nt < 8; nt++) {
                float p0 = __expf(s[mt][nt][0] - mnLo);
                float p1 = __expf(s[mt][nt][1] - mnLo);
                float p2 = __expf(s[mt][nt][2] - mnHi);
                float p3 = __expf(s[mt][nt][3] - mnHi);
                rsLo += p0 + p1;
                rsHi += p2 + p3;
                s[mt][nt][0] = p0; s[mt][nt][1] = p1;
                s[mt][nt][2] = p2; s[mt][nt][3] = p3;
                o[mt][nt][0] *= corrLo; o[mt][nt][1] *= corrLo;
                o[mt][nt][2] *= corrHi; o[mt][nt][3] *= corrHi;
            }
            rsLo += __shfl_xor_sync(0xffffffffu, rsLo, 1);
            rsLo += __shfl_xor_sync(0xffffffffu, rsLo, 2);
            rsHi += __shfl_xor_sync(0xffffffffu, rsHi, 1);
            rsHi += __shfl_xor_sync(0xffffffffu, rsHi, 2);
            ls[mt][0] = ls[mt][0] * corrLo + rsLo;
            ls[mt][1] = ls[mt][1] * corrHi + rsHi;
        }

        #pragma unroll
        for (int kk = 0; kk < 4; kk++) {
            uint32_t af[2][4];
            #pragma unroll
            for (int mt = 0; mt < 2; mt++) {
                af[mt][0] = h2u(s[mt][2 * kk][0],     s[mt][2 * kk][1]);
                af[mt][1] = h2u(s[mt][2 * kk][2],     s[mt][2 * kk][3]);
                af[mt][2] = h2u(s[mt][2 * kk + 1][0], s[mt][2 * kk + 1][1]);
                af[mt][3] = h2u(s[mt][2 * kk + 1][2], s[mt][2 * kk + 1][3]);
            }
            #pragma unroll
            for (int nt = 0; nt < 8; nt++) {
                uint2 v2 = *(const uint2*)&smha[8192 + kbo
                                                + (kk * 8 + nt) * 128 + lane * 4];
                mma_f16(o[0][nt], af[0], v2.x, v2.y);
                mma_f16(o[1][nt], af[1], v2.x, v2.y);
            }
        }
    }

    // store unnormalized partials in fp16 + (m, l)
    __half* Opart = g_Parth[split];
    #pragma unroll
    for (int mt = 0; mt < 2; mt++) {
        const int rowLo = q0 + 32 * w + 16 * mt + gid;
        __half* OgLo = Opart + ((size_t)b * NQS + rowLo) * DM + h * DH;
        __half* OgHi = OgLo + 8 * (size_t)DM;
        #pragma unroll
        for (int nt = 0; nt < 8; nt++) {
            int col = nt * 8 + 2 * tig;
            *(uint32_t*)(OgLo + col) = h2u(o[mt][nt][0], o[mt][nt][1]);
            *(uint32_t*)(OgHi + col) = h2u(o[mt][nt][2], o[mt][nt][3]);
        }
        if (tig == 0) {
            int mi = (b * 8 + h) * 1024 + rowLo;
            g_M[split][mi]     = mx[mt][0];
            g_L[split][mi]     = ls[mt][0];
            g_M[split][mi + 8] = mx[mt][1];
            g_L[split][mi + 8] = ls[mt][1];
        }
    }
}

// ===========================================================================
// Merge the NSPLIT KV splits (fp16 partials); emit fp16 A operand.
// One thread per 8 elements (all share one (row,head) -> one (m,l) gather),
// uint4 loads per split. grid = BATCH*NQS*DM/8/256 = 1024 blocks.
// ===========================================================================
__global__ __launch_bounds__(256) void merge_kernel()
{
    const size_t i = (size_t)blockIdx.x * 256 + threadIdx.x;   // per 8 halves
    const size_t e = i * 8;
    const size_t row = e / DM;
    const int d  = (int)(e % DM);
    const int b  = (int)(row >> 10);
    const int q  = (int)(row & 1023);
    const int h  = d >> 6;                 // all 8 elems in same head block
    const int mi = (b * 8 + h) * 1024 + q;

    float m[NSPLIT], l[NSPLIT];
    float ms = -1e30f;
    #pragma unroll
    for (int s = 0; s < NSPLIT; s++) {
        m[s] = g_M[s][mi];
        l[s] = g_L[s][mi];
        ms = fmaxf(ms, m[s]);
    }
    float den = 0.f;
    float a[NSPLIT];
    #pragma unroll
    for (int s = 0; s < NSPLIT; s++) {
        a[s] = __expf(m[s] - ms);
        den += l[s] * a[s];
    }
    const float inv = 1.f / den;

    float acc[8] = {0.f, 0.f, 0.f, 0.f, 0.f, 0.f, 0.f, 0.f};
    #pragma unroll
    for (int s = 0; s < NSPLIT; s++) {
        uint4 pv = *(const uint4*)&g_Parth[s][e];
        float2 p0 = u2f2(pv.x), p1 = u2f2(pv.y);
        float2 p2 = u2f2(pv.z), p3 = u2f2(pv.w);
        acc[0] += p0.x * a[s]; acc[1] += p0.y * a[s];
        acc[2] += p1.x * a[s]; acc[3] += p1.y * a[s];
        acc[4] += p2.x * a[s]; acc[5] += p2.y * a[s];
        acc[6] += p3.x * a[s]; acc[7] += p3.y * a[s];
    }
    uint2 outv;
    uint2 outw;
    outv.x = h2u(acc[0] * inv, acc[1] * inv);
    outv.y = h2u(acc[2] * inv, acc[3] * inv);
    outw.x = h2u(acc[4] * inv, acc[5] * inv);
    outw.y = h2u(acc[6] * inv, acc[7] * inv);
    *(uint4*)&g_AOh[e] = make_uint4(outv.x, outv.y, outw.x, outw.y);
}

// ---------------------------------------------------------------------------
// Launch
// ---------------------------------------------------------------------------
extern "C" void kernel_launch(void* const* d_in, const int* in_sizes, int n_in,
                              void* d_out, int out_size)
{
    const float* x    = (const float*)d_in[0];
    const float* ctx  = (const float*)d_in[1];
    const float* bias = (const float*)d_in[2];
    const float* Wq   = (const float*)d_in[3];
    const float* Wk   = (const float*)d_in[4];
    const float* Wv   = (const float*)d_in[5];
    const float* Wo   = (const float*)d_in[6];
    const float* bo   = (const float*)d_in[7];
    float* out = (float*)d_out;

    cudaFuncSetAttribute(gemm_qkv_kernel,
                         cudaFuncAttributeMaxDynamicSharedMemorySize, GEMM_SMEM);
    cudaFuncSetAttribute(gemm_o_kernel,
                         cudaFuncAttributeMaxDynamicSharedMemorySize, GEMM_SMEM);
    cudaFuncSetAttribute(attn_kernel,
                         cudaFuncAttributeMaxDynamicSharedMemorySize, ATTN_SMEM);

    conv_all_kernel<<<CONV_BLOCKS, 256>>>(x, ctx, Wq, Wk, Wv, Wo);
    gemm_qkv_kernel<<<1280, 128, GEMM_SMEM>>>();
    attn_kernel<<<dim3((NQS / 128) * NSPLIT, NHEADS, BATCH),
                  dim3(128), ATTN_SMEM>>>(bias);
    merge_kernel<<<(BATCH * NQS * DM / 8) / 256, 256>>>();
    gemm_o_kernel<<<dim3(8, 32), 128, GEMM_SMEM>>>(bo, out);
}

// round 15
// speedup vs baseline: 1.0519x; 1.0145x over previous
#include <cuda_runtime.h>
#include <cuda_fp16.h>
#include <cstdint>
#include <math.h>

#define NHEADS 8
#define DH     64
#define BATCH  4
#define NQS    1024
#define NKS    2048
#define DM     512
#define NSPLIT 8

// fp16 copies of inputs (converted once per run).
__device__ __half g_Xh  [(size_t)BATCH * NQS * DM];
__device__ __half g_Ctxh[(size_t)BATCH * NKS * DM];
__device__ __half g_Wqh[DM * DM];
__device__ __half g_Wkh[DM * DM];
__device__ __half g_Wvh[DM * DM];
__device__ __half g_Woh[DM * DM];
// Packed fp16 fragment buffers (mma-fragment order).
__device__ __half g_Qh[(size_t)BATCH * NQS * DM];
__device__ __half g_Kh[(size_t)BATCH * NKS * DM];
__device__ __half g_Vh[(size_t)BATCH * NKS * DM];
// Split-KV partial outputs (unnormalized, fp16) + (m, l) per row per split.
__device__ __half g_Parth[NSPLIT][(size_t)BATCH * NQS * DM];
__device__ float  g_M[NSPLIT][BATCH * NHEADS * NQS];
__device__ float  g_L[NSPLIT][BATCH * NHEADS * NQS];
// Merged attention output in fp16 (A operand of the output GEMM).
__device__ __half g_AOh[(size_t)BATCH * NQS * DM];

// ===========================================================================
// Helpers
// ===========================================================================
__device__ __forceinline__ uint32_t smem_u32(const void* p) {
    uint32_t a;
    asm("{ .reg .u64 t; cvta.to.shared.u64 t, %1; cvt.u32.u64 %0, t; }"
        : "=r"(a) : "l"(p));
    return a;
}
__device__ __forceinline__ void mma_f16(float c[4], const uint32_t a[4],
                                        uint32_t b0, uint32_t b1) {
    asm volatile(
        "mma.sync.aligned.m16n8k16.row.col.f32.f16.f16.f32 "
        "{%0,%1,%2,%3}, {%4,%5,%6,%7}, {%8,%9}, {%0,%1,%2,%3};"
        : "+f"(c[0]), "+f"(c[1]), "+f"(c[2]), "+f"(c[3])
        : "r"(a[0]), "r"(a[1]), "r"(a[2]), "r"(a[3]), "r"(b0), "r"(b1));
}
__device__ __forceinline__ void ldsm_x4(uint32_t r[4], uint32_t addr) {
    asm volatile("ldmatrix.sync.aligned.m8n8.x4.shared.b16 {%0,%1,%2,%3}, [%4];"
                 : "=r"(r[0]), "=r"(r[1]), "=r"(r[2]), "=r"(r[3]) : "r"(addr));
}
__device__ __forceinline__ void ldsm_x2(uint32_t r[2], uint32_t addr) {
    asm volatile("ldmatrix.sync.aligned.m8n8.x2.shared.b16 {%0,%1}, [%2];"
                 : "=r"(r[0]), "=r"(r[1]) : "r"(addr));
}
__device__ __forceinline__ uint32_t h2u(float lo, float hi) {
    __half2 v = __floats2half2_rn(lo, hi);
    return *(uint32_t*)&v;
}
__device__ __forceinline__ float2 u2f2(uint32_t u) {
    return __half22float2(*reinterpret_cast<const __half2*>(&u));
}
__device__ __forceinline__ void cp_async16(uint32_t s, const void* g) {
    asm volatile("cp.async.ca.shared.global [%0], [%1], 16;"
                 :: "r"(s), "l"(g) : "memory");
}
__device__ __forceinline__ void cp_commit() {
    asm volatile("cp.async.commit_group;" ::: "memory");
}
template<int N> __device__ __forceinline__ void cp_wait() {
    asm volatile("cp.async.wait_group %0;" :: "n"(N) : "memory");
}

// ===========================================================================
// Fused fp32 -> fp16 conversion of x, ctx and the 4 weights (one launch).
// ===========================================================================
#define NX4 (BATCH * NQS * DM / 4)
#define NC4 (BATCH * NKS * DM / 4)
#define NW4 (DM * DM / 4)
#define CONV_BLOCKS ((NX4 + NC4 + 4 * NW4) / 256)

__global__ __launch_bounds__(256) void conv_all_kernel(
    const float* __restrict__ x,  const float* __restrict__ ctx,
    const float* __restrict__ w0, const float* __restrict__ w1,
    const float* __restrict__ w2, const float* __restrict__ w3)
{
    const int i = blockIdx.x * 256 + threadIdx.x;
    const float* src;
    __half* dst;
    int j;
    if (i < NX4)                 { src = x;   dst = g_Xh;   j = i; }
    else if (i < NX4 + NC4)      { src = ctx; dst = g_Ctxh; j = i - NX4; }
    else {
        const int k = i - NX4 - NC4;
        const int t = k >> 16;
        j = k & 65535;
        src = (t == 0) ? w0 : (t == 1) ? w1 : (t == 2) ? w2 : w3;
        dst = (t == 0) ? g_Wqh : (t == 1) ? g_Wkh : (t == 2) ? g_Wvh : g_Woh;
    }
    float4 v = ((const float4*)src)[j];
    *(uint2*)&dst[(size_t)j * 4] = make_uint2(h2u(v.x, v.y), h2u(v.z, v.w));
}

// ===========================================================================
// GEMM mainloop core: C[M,512] = A[M,512] @ W[512,512]^T, fp16 mma.
// CTA tile 128(M) x 64(N), BK=32 halves, 3-stage cp.async, 128 threads.
// PIPELINE INVARIANT: one commit_group per iteration (empty commits in tail).
// ===========================================================================
#define GBKH    32
#define GPITCHH 40
#define GA_H    (128 * GPITCHH)
#define GB_H    (64 * GPITCHH)
#define GSTG_H  (GA_H + GB_H)
#define GEMM_SMEM (3 * GSTG_H * 2)

__device__ __forceinline__ void gemm_mainloop(
    const __half* __restrict__ A, const __half* __restrict__ W,
    int m0, int n0, uint32_t sb, float acc[4][4][4],
    int lane, int wm, int wn)
{
    const int tid = threadIdx.x;

    auto stage_load = [&](int buf, int ks) {
        const int k0 = ks * GBKH;
        const uint32_t sA = sb + (uint32_t)(buf * GSTG_H) * 2u;
        const uint32_t sB = sA + (uint32_t)GA_H * 2u;
        #pragma unroll
        for (int i = 0; i < 4; i++) {
            int idx = tid + 128 * i;
            int r = idx >> 2, c = (idx & 3) * 8;
            cp_async16(sA + (uint32_t)(r * GPITCHH + c) * 2u,
                       A + (size_t)(m0 + r) * DM + k0 + c);
        }
        #pragma unroll
        for (int i = 0; i < 2; i++) {
            int idx = tid + 128 * i;
            int r = idx >> 2, c = (idx & 3) * 8;
            cp_async16(sB + (uint32_t)(r * GPITCHH + c) * 2u,
                       W + (size_t)(n0 + r) * DM + k0 + c);
        }
        cp_commit();
    };

    const int NST = DM / GBKH;
    stage_load(0, 0);
    stage_load(1, 1);
    stage_load(2, 2);

    const int aRow = ((lane >> 3) & 1) * 8 + (lane & 7);
    const int aK   = ((lane >> 4) & 1) * 8;
    const int bRow = lane & 7;
    const int bK   = ((lane >> 3) & 1) * 8;

    int buf = 0;
    for (int ks = 0; ks < NST; ++ks) {
        cp_wait<2>();
        __syncthreads();

        const uint32_t aBase = sb + (uint32_t)(buf * GSTG_H) * 2u;
        const uint32_t bBase = aBase + (uint32_t)GA_H * 2u;

        #pragma unroll
        for (int kst = 0; kst < 2; kst++) {
            uint32_t af[4][4];
            #pragma unroll
            for (int mt = 0; mt < 4; mt++)
                ldsm_x4(af[mt], aBase
                        + (uint32_t)((wm + mt * 16 + aRow) * GPITCHH
                                     + kst * 16 + aK) * 2u);
            uint32_t bf[4][2];
            #pragma unroll
            for (int nt = 0; nt < 4; nt++)
                ldsm_x2(bf[nt], bBase
                        + (uint32_t)((wn + nt * 8 + bRow) * GPITCHH
                                     + kst * 16 + bK) * 2u);
            #pragma unroll
            for (int mt = 0; mt < 4; mt++)
                #pragma unroll
                for (int nt = 0; nt < 4; nt++)
                    mma_f16(acc[mt][nt], af[mt], bf[nt][0], bf[nt][1]);
        }
        __syncthreads();
        if (ks + 3 < NST) stage_load(buf, ks + 3);
        else              cp_commit();
        buf = (buf == 2) ? 0 : buf + 1;
    }
}

// ---------------------------------------------------------------------------
// Fused Q/K/V projection GEMM. Linear grid: [0,256)=Q, [256,768)=K,
// [768,1280)=V. Epilogue: Q/K store uint32 (half2) pairs (contiguous, 4B
// aligned); V stores its pair at idx and idx+16 (g -> g+1 stride in layout).
// ---------------------------------------------------------------------------
__global__ __launch_bounds__(128, 4) void gemm_qkv_kernel()
{
    extern __shared__ __half smh[];
    const uint32_t sb = smem_u32(smh);

    const int tid  = threadIdx.x;
    const int w    = tid >> 5;
    const int lane = tid & 31;
    const int gid  = lane >> 2;
    const int tig  = lane & 3;
    const int wm   = (w >> 1) * 64;
    const int wn   = (w & 1) * 32;

    int id = blockIdx.x, mode;
    const __half *A, *W;
    __half *C;
    if (id < 256)      { mode = 1; A = g_Xh;   W = g_Wqh; C = g_Qh; }
    else if (id < 768) { mode = 2; id -= 256; A = g_Ctxh; W = g_Wkh; C = g_Kh; }
    else               { mode = 3; id -= 768; A = g_Ctxh; W = g_Wvh; C = g_Vh; }
    const int m0 = (id >> 3) * 128;
    const int n0 = (id & 7) * 64;

    float acc[4][4][4];
    #pragma unroll
    for (int mt = 0; mt < 4; mt++)
        #pragma unroll
        for (int nt = 0; nt < 4; nt++)
            #pragma unroll
            for (int q = 0; q < 4; q++) acc[mt][nt][q] = 0.f;

    gemm_mainloop(A, W, m0, n0, sb, acc, lane, wm, wn);

    #pragma unroll
    for (int mt = 0; mt < 4; mt++) {
        #pragma unroll
        for (int nt = 0; nt < 4; nt++) {
            #pragma unroll
            for (int qp = 0; qp < 2; qp++) {       // q-pairs (0,1) and (2,3)
                const int m   = m0 + wm + mt * 16 + gid + 8 * qp;
                const int col = n0 + wn + nt * 8 + 2 * tig;   // even col
                const int h = col >> 6, d = col & 63;         // d even
                float v0 = acc[mt][nt][2 * qp];
                float v1 = acc[mt][nt][2 * qp + 1];
                size_t idx;
                if (mode == 1) {
                    int b  = m >> 10, qq = m & 1023;
                    int t  = qq >> 4, g = qq & 7, rh = (qq >> 3) & 1;
                    int kk = d >> 4, hi = (d >> 3) & 1;
                    int tq = (d & 7) >> 1;
                    idx = ((((size_t)((b * 8 + h) * 64 + t) * 4 + kk) * 256)
                          + (g * 4 + tq) * 8 + (rh + 2 * hi) * 2);
                    v0 *= 0.125f; v1 *= 0.125f;
                    *(uint32_t*)&C[idx] = h2u(v0, v1);
                } else if (mode == 2) {
                    int b = m >> 11, n = m & 2047;
                    int kt = n >> 6, ri = n & 63;
                    int nt2 = ri >> 3, g = ri & 7;
                    int kk = d >> 4, hi = (d >> 3) & 1;
                    int t = (d & 7) >> 1;
                    idx = (size_t)((b * 32 + kt) * 8 + h) * 4096
                          + (kk * 8 + nt2) * 128 + (g * 4 + t) * 4 + hi * 2;
                    *(uint32_t*)&C[idx] = h2u(v0, v1);
                } else {
                    int b = m >> 11, n = m & 2047;
                    int kt = n >> 6, kr = n & 63;
                    int kk = kr >> 4, hi = (kr >> 3) & 1;
                    int t = (kr & 7) >> 1, ev = kr & 1;
                    int nt2 = d >> 3, g = d & 7;
                    idx = (size_t)((b * 32 + kt) * 8 + h) * 4096
                          + (kk * 8 + nt2) * 128 + (g * 4 + t) * 4
                          + hi * 2 + ev;
                    // col pair (d, d+1): g -> g+1 means +16 halves in layout
                    C[idx]      = __float2half_rn(v0);
                    C[idx + 16] = __float2half_rn(v1);
                }
            }
        }
    }
}

// ---------------------------------------------------------------------------
// Output GEMM: out = g_AOh @ Wo^T + bo.  grid (8 n, 32 m).
// ---------------------------------------------------------------------------
__global__ __launch_bounds__(128, 4) void gemm_o_kernel(
    const float* __restrict__ bias, float* __restrict__ out)
{
    extern __shared__ __half smh[];
    const uint32_t sb = smem_u32(smh);

    const int tid  = threadIdx.x;
    const int w    = tid >> 5;
    const int lane = tid & 31;
    const int gid  = lane >> 2;
    const int tig  = lane & 3;
    const int wm   = (w >> 1) * 64;
    const int wn   = (w & 1) * 32;
    const int n0   = blockIdx.x * 64;
    const int m0   = blockIdx.y * 128;

    float acc[4][4][4];
    #pragma unroll
    for (int mt = 0; mt < 4; mt++)
        #pragma unroll
        for (int nt = 0; nt < 4; nt++)
            #pragma unroll
            for (int q = 0; q < 4; q++) acc[mt][nt][q] = 0.f;

    gemm_mainloop(g_AOh, g_Woh, m0, n0, sb, acc, lane, wm, wn);

    #pragma unroll
    for (int mt = 0; mt < 4; mt++) {
        const int r0 = m0 + wm + mt * 16 + gid;
        #pragma unroll
        for (int nt = 0; nt < 4; nt++) {
            const int col = n0 + wn + nt * 8 + 2 * tig;
            const float b0 = bias[col], b1 = bias[col + 1];
            *(float2*)(out + (size_t)r0 * DM + col) =
                make_float2(acc[mt][nt][0] + b0, acc[mt][nt][1] + b1);
            *(float2*)(out + (size_t)(r0 + 8) * DM + col) =
                make_float2(acc[mt][nt][2] + b0, acc[mt][nt][3] + b1);
        }
    }
}

// ===========================================================================
// Flash attention, fp16 mma, f32 accumulate, P in registers, SPLIT-KV x8.
// Grid (64, 8, 4): blockIdx.x = qt*8 + split; each CTA does 4 KV tiles.
// ===========================================================================
#define ATTN_SMEM 49152
#define KV_SPLIT_TILES (32 / NSPLIT)

__global__ __launch_bounds__(128, 3) void attn_kernel(const float* __restrict__ bias)
{
    extern __shared__ __half smha[];
    const uint32_t sb = smem_u32(smha);

    const int tid   = threadIdx.x;
    const int w     = tid >> 5;
    const int lane  = tid & 31;
    const int gid   = lane >> 2;
    const int tig   = lane & 3;
    const int split = blockIdx.x & (NSPLIT - 1);
    const int qt    = blockIdx.x / NSPLIT;
    const int q0    = qt * 128;
    const int h     = blockIdx.y;
    const int b     = blockIdx.z;
    const int kb0   = split * KV_SPLIT_TILES;

    {
        const __half* gq = g_Qh + (size_t)((b * 8 + h) * 64 + qt * 8) * 1024;
        #pragma unroll
        for (int i = 0; i < 8; i++) {
            int off = i * 1024 + tid * 8;
            cp_async16(sb + (16384 + off) * 2, gq + off);
        }
    }
    {
        const __half* gk = g_Kh + ((size_t)(b * 32 + kb0) * 8 + h) * 4096;
        const __half* gv = g_Vh + ((size_t)(b * 32 + kb0) * 8 + h) * 4096;
        #pragma unroll
        for (int i = 0; i < 4; i++) {
            int off = i * 1024 + tid * 8;
            cp_async16(sb + ((kb0 & 1) * 4096 + off) * 2, gk + off);
            cp_async16(sb + (8192 + (kb0 & 1) * 4096 + off) * 2, gv + off);
        }
    }
    cp_commit();

    float o[2][8][4];
    #pragma unroll
    for (int mt = 0; mt < 2; mt++)
        #pragma unroll
        for (int nt = 0; nt < 8; nt++)
            #pragma unroll
            for (int q = 0; q < 4; q++) o[mt][nt][q] = 0.f;
    float mx[2][2] = {{-1e30f, -1e30f}, {-1e30f, -1e30f}};
    float ls[2][2] = {{0.f, 0.f}, {0.f, 0.f}};

    const int qbase = 16384 + w * 2048;

    for (int kb = kb0; kb < kb0 + KV_SPLIT_TILES; kb++) {
        cp_wait<0>();
        __syncthreads();

        if (kb + 1 < kb0 + KV_SPLIT_TILES) {
            const int nb = (kb + 1) & 1;
            const __half* gk = g_Kh + ((size_t)(b * 32 + kb + 1) * 8 + h) * 4096;
            const __half* gv = g_Vh + ((size_t)(b * 32 + kb + 1) * 8 + h) * 4096;
            #pragma unroll
            for (int i = 0; i < 4; i++) {
                int off = i * 1024 + tid * 8;
                cp_async16(sb + (nb * 4096 + off) * 2, gk + off);
                cp_async16(sb + (8192 + nb * 4096 + off) * 2, gv + off);
            }
            cp_commit();
        }

        const int kbo = (kb & 1) * 4096;

        float s[2][8][4];
        #pragma unroll
        for (int mt = 0; mt < 2; mt++)
            #pragma unroll
            for (int nt = 0; nt < 8; nt++)
                #pragma unroll
                for (int q = 0; q < 4; q++) s[mt][nt][q] = 0.f;

        #pragma unroll
        for (int kk = 0; kk < 4; kk++) {
            uint32_t af[2][4];
            #pragma unroll
            for (int mt = 0; mt < 2; mt++) {
                float4 a4 = *(const float4*)&smha[qbase + mt * 1024
                                                  + kk * 256 + lane * 8];
                af[mt][0] = __float_as_uint(a4.x); af[mt][1] = __float_as_uint(a4.y);
                af[mt][2] = __float_as_uint(a4.z); af[mt][3] = __float_as_uint(a4.w);
            }
            #pragma unroll
            for (int nt = 0; nt < 8; nt++) {
                uint2 k2 = *(const uint2*)&smha[kbo + (kk * 8 + nt) * 128 + lane * 4];
                mma_f16(s[0][nt], af[0], k2.x, k2.y);
                mma_f16(s[1][nt], af[1], k2.x, k2.y);
            }
        }

        #pragma unroll
        for (int mt = 0; mt < 2; mt++) {
            const float* bLo = bias
                + ((size_t)b * NQS + q0 + 32 * w + 16 * mt + gid) * NKS + kb * 64;
            const float* bHi = bLo + 8 * (size_t)NKS;

            float rmLo = -1e30f, rmHi = -1e30f;
            #pragma unroll
            for (int nt = 0; nt < 8; nt++) {
                float2 bl = *(const float2*)(bLo + nt * 8 + 2 * tig);
                float2 bh = *(const float2*)(bHi + nt * 8 + 2 * tig);
                s[mt][nt][0] += bl.x;  s[mt][nt][1] += bl.y;
                s[mt][nt][2] += bh.x;  s[mt][nt][3] += bh.y;
                rmLo = fmaxf(rmLo, fmaxf(s[mt][nt][0], s[mt][nt][1]));
                rmHi = fmaxf(rmHi, fmaxf(s[mt][nt][2], s[mt][nt][3]));
            }
            rmLo = fmaxf(rmLo, __shfl_xor_sync(0xffffffffu, rmLo, 1));
            rmLo = fmaxf(rmLo, __shfl_xor_sync(0xffffffffu, rmLo, 2));
            rmHi = fmaxf(rmHi, __shfl_xor_sync(0xffffffffu, rmHi, 1));
            rmHi = fmaxf(rmHi, __shfl_xor_sync(0xffffffffu, rmHi, 2));

            const float mnLo = fmaxf(mx[mt][0], rmLo);
            const float mnHi = fmaxf(mx[mt][1], rmHi);
            const float corrLo = __expf(mx[mt][0] - mnLo);
            const float corrHi = __expf(mx[mt][1] - mnHi);
            mx[mt][0] = mnLo; mx[mt][1] = mnHi;

            float rsLo = 0.f, rsHi = 0.f;
            #pragma unroll
            for (int nt = 0; nt < 8; nt++) {
                float p0 = __expf(s[mt][nt][0] - mnLo);
                float p1 = __expf(s[mt][nt][1] - mnLo);
                float p2 = __expf(s[mt][nt][2] - mnHi);
                float p3 = __expf(s[mt][nt][3] - mnHi);
                rsLo += p0 + p1;
                rsHi += p2 + p3;
                s[mt][nt][0] = p0; s[mt][nt][1] = p1;
                s[mt][nt][2] = p2; s[mt][nt][3] = p3;
                o[mt][nt][0] *= corrLo; o[mt][nt][1] *= corrLo;
                o[mt][nt][2] *= corrHi; o[mt][nt][3] *= corrHi;
            }
            rsLo += __shfl_xor_sync(0xffffffffu, rsLo, 1);
            rsLo += __shfl_xor_sync(0xffffffffu, rsLo, 2);
            rsHi += __shfl_xor_sync(0xffffffffu, rsHi, 1);
            rsHi += __shfl_xor_sync(0xffffffffu, rsHi, 2);
            ls[mt][0] = ls[mt][0] * corrLo + rsLo;
            ls[mt][1] = ls[mt][1] * corrHi + rsHi;
        }

        #pragma unroll
        for (int kk = 0; kk < 4; kk++) {
            uint32_t af[2][4];
            #pragma unroll
            for (int mt = 0; mt < 2; mt++) {
                af[mt][0] = h2u(s[mt][2 * kk][0],     s[mt][2 * kk][1]);
                af[mt][1] = h2u(s[mt][2 * kk][2],     s[mt][2 * kk][3]);
                af[mt][2] = h2u(s[mt][2 * kk + 1][0], s[mt][2 * kk + 1][1]);
                af[mt][3] = h2u(s[mt][2 * kk + 1][2], s[mt][2 * kk + 1][3]);
            }
            #pragma unroll
            for (int nt = 0; nt < 8; nt++) {
                uint2 v2 = *(const uint2*)&smha[8192 + kbo
                                                + (kk * 8 + nt) * 128 + lane * 4];
                mma_f16(o[0][nt], af[0], v2.x, v2.y);
                mma_f16(o[1][nt], af[1], v2.x, v2.y);
            }
        }
    }

    // store unnormalized partials in fp16 + (m, l)
    __half* Opart = g_Parth[split];
    #pragma unroll
    for (int mt = 0; mt < 2; mt++) {
        const int rowLo = q0 + 32 * w + 16 * mt + gid;
        __half* OgLo = Opart + ((size_t)b * NQS + rowLo) * DM + h * DH;
        __half* OgHi = OgLo + 8 * (size_t)DM;
        #pragma unroll
        for (int nt = 0; nt < 8; nt++) {
            int col = nt * 8 + 2 * tig;
            *(uint32_t*)(OgLo + col) = h2u(o[mt][nt][0], o[mt][nt][1]);
            *(uint32_t*)(OgHi + col) = h2u(o[mt][nt][2], o[mt][nt][3]);
        }
        if (tig == 0) {
            int mi = (b * 8 + h) * 1024 + rowLo;
            g_M[split][mi]     = mx[mt][0];
            g_L[split][mi]     = ls[mt][0];
            g_M[split][mi + 8] = mx[mt][1];
            g_L[split][mi + 8] = ls[mt][1];
        }
    }
}

// ===========================================================================
// Merge the NSPLIT KV splits (fp16 partials); emit fp16 A operand.
// One thread per 8 elements, uint4 loads per split.
// ===========================================================================
__global__ __launch_bounds__(256) void merge_kernel()
{
    const size_t i = (size_t)blockIdx.x * 256 + threadIdx.x;   // per 8 halves
    const size_t e = i * 8;
    const size_t row = e / DM;
    const int d  = (int)(e % DM);
    const int b  = (int)(row >> 10);
    const int q  = (int)(row & 1023);
    const int h  = d >> 6;
    const int mi = (b * 8 + h) * 1024 + q;

    float m[NSPLIT], l[NSPLIT];
    float ms = -1e30f;
    #pragma unroll
    for (int s = 0; s < NSPLIT; s++) {
        m[s] = g_M[s][mi];
        l[s] = g_L[s][mi];
        ms = fmaxf(ms, m[s]);
    }
    float den = 0.f;
    float a[NSPLIT];
    #pragma unroll
    for (int s = 0; s < NSPLIT; s++) {
        a[s] = __expf(m[s] - ms);
        den += l[s] * a[s];
    }
    const float inv = 1.f / den;

    float acc[8] = {0.f, 0.f, 0.f, 0.f, 0.f, 0.f, 0.f, 0.f};
    #pragma unroll
    for (int s = 0; s < NSPLIT; s++) {
        uint4 pv = *(const uint4*)&g_Parth[s][e];
        float2 p0 = u2f2(pv.x), p1 = u2f2(pv.y);
        float2 p2 = u2f2(pv.z), p3 = u2f2(pv.w);
        acc[0] += p0.x * a[s]; acc[1] += p0.y * a[s];
        acc[2] += p1.x * a[s]; acc[3] += p1.y * a[s];
        acc[4] += p2.x * a[s]; acc[5] += p2.y * a[s];
        acc[6] += p3.x * a[s]; acc[7] += p3.y * a[s];
    }
    *(uint4*)&g_AOh[e] = make_uint4(
        h2u(acc[0] * inv, acc[1] * inv), h2u(acc[2] * inv, acc[3] * inv),
        h2u(acc[4] * inv, acc[5] * inv), h2u(acc[6] * inv, acc[7] * inv));
}

// ---------------------------------------------------------------------------
// Launch
// ---------------------------------------------------------------------------
extern "C" void kernel_launch(void* const* d_in, const int* in_sizes, int n_in,
                              void* d_out, int out_size)
{
    const float* x    = (const float*)d_in[0];
    const float* ctx  = (const float*)d_in[1];
    const float* bias = (const float*)d_in[2];
    const float* Wq   = (const float*)d_in[3];
    const float* Wk   = (const float*)d_in[4];
    const float* Wv   = (const float*)d_in[5];
    const float* Wo   = (const float*)d_in[6];
    const float* bo   = (const float*)d_in[7];
    float* out = (float*)d_out;

    cudaFuncSetAttribute(gemm_qkv_kernel,
                         cudaFuncAttributeMaxDynamicSharedMemorySize, GEMM_SMEM);
    cudaFuncSetAttribute(gemm_o_kernel,
                         cudaFuncAttributeMaxDynamicSharedMemorySize, GEMM_SMEM);
    cudaFuncSetAttribute(attn_kernel,
                         cudaFuncAttributeMaxDynamicSharedMemorySize, ATTN_SMEM);

    conv_all_kernel<<<CONV_BLOCKS, 256>>>(x, ctx, Wq, Wk, Wv, Wo);
    gemm_qkv_kernel<<<1280, 128, GEMM_SMEM>>>();
    attn_kernel<<<dim3((NQS / 128) * NSPLIT, NHEADS, BATCH),
                  dim3(128), ATTN_SMEM>>>(bias);
    merge_kernel<<<(BATCH * NQS * DM / 8) / 256, 256>>>();
    gemm_o_kernel<<<dim3(8, 32), 128, GEMM_SMEM>>>(bo, out);
}